// round 1
// baseline (speedup 1.0000x reference)
#include <cuda_runtime.h>
#include <math.h>

#define Nn 64
#define Tt 512
#define Dd 1024
#define Hh 1024
#define G4 4096   // 4*Hh

// Scratch (device globals: allocation-free rule)
__device__ float g_xw[(size_t)Nn * Tt * G4];  // [N*T, 4H] input projection, 512 MB
__device__ float g_c[Nn * Hh];                // cell state

// ---------------------------------------------------------------------------
// zero the cell state (c0 = 0) at the start of every launch
// ---------------------------------------------------------------------------
__global__ void zero_c_kernel() {
    int i = blockIdx.x * blockDim.x + threadIdx.x;
    if (i < Nn * Hh) g_c[i] = 0.0f;
}

// ---------------------------------------------------------------------------
// xW = x[N*T, D] @ Wx[D, 4H] + b   -> g_xw
// Classic 128x128x8 SGEMM, 256 threads, 8x8 microtile.
// ---------------------------------------------------------------------------
__global__ void __launch_bounds__(256) sgemm_xw(const float* __restrict__ A,
                                                const float* __restrict__ B,
                                                const float* __restrict__ bias) {
    const int K = Dd;
    const int Nc = G4;

    __shared__ float As[8][128];   // transposed A tile: As[k][m]
    __shared__ float Bs[8][128];   // Bs[k][n]

    int tid = threadIdx.x;
    int bx = blockIdx.x;   // column tile (0..31)
    int by = blockIdx.y;   // row tile    (0..255)

    // global-load mapping
    int arow = tid >> 1;            // 0..127
    int acol = (tid & 1) * 4;       // 0 or 4
    int brow = tid >> 5;            // 0..7
    int bcol = (tid & 31) * 4;      // 0..124

    const float* Ap = A + (size_t)(by * 128 + arow) * K + acol;
    const float* Bp = B + (size_t)brow * Nc + bx * 128 + bcol;

    int tx = tid & 15;   // 0..15  (8 output cols each)
    int ty = tid >> 4;   // 0..15  (8 output rows each)

    float acc[8][8];
#pragma unroll
    for (int i = 0; i < 8; i++)
#pragma unroll
        for (int j = 0; j < 8; j++) acc[i][j] = 0.0f;

    for (int k0 = 0; k0 < K; k0 += 8) {
        float4 a4 = *(const float4*)Ap;  Ap += 8;
        float4 b4 = *(const float4*)Bp;  Bp += (size_t)8 * Nc;

        As[acol + 0][arow] = a4.x;
        As[acol + 1][arow] = a4.y;
        As[acol + 2][arow] = a4.z;
        As[acol + 3][arow] = a4.w;
        *(float4*)&Bs[brow][bcol] = b4;
        __syncthreads();

#pragma unroll
        for (int kk = 0; kk < 8; kk++) {
            float af[8], bf[8];
            *(float4*)(af + 0) = *(const float4*)&As[kk][ty * 8 + 0];
            *(float4*)(af + 4) = *(const float4*)&As[kk][ty * 8 + 4];
            *(float4*)(bf + 0) = *(const float4*)&Bs[kk][tx * 8 + 0];
            *(float4*)(bf + 4) = *(const float4*)&Bs[kk][tx * 8 + 4];
#pragma unroll
            for (int i = 0; i < 8; i++)
#pragma unroll
                for (int j = 0; j < 8; j++) acc[i][j] += af[i] * bf[j];
        }
        __syncthreads();
    }

    // epilogue: add bias, store
    float bv[8];
    const float* bp = bias + bx * 128 + tx * 8;
#pragma unroll
    for (int j = 0; j < 8; j++) bv[j] = bp[j];

#pragma unroll
    for (int i = 0; i < 8; i++) {
        size_t row = (size_t)(by * 128 + ty * 8 + i);
        float* Cp = g_xw + row * Nc + bx * 128 + tx * 8;
#pragma unroll
        for (int j = 0; j < 8; j++) Cp[j] = acc[i][j] + bv[j];
    }
}

// ---------------------------------------------------------------------------
// One LSTM timestep, fully fused:
//   a[n, :] = g_xw[n, t, :] + h_prev[n, :] @ Wh        (block computes 64x32
//   a-columns = 4 gates x 8 h-indices), then gates + c/h update.
// Grid = 128 blocks (8 h-indices each), 256 threads.
// ---------------------------------------------------------------------------
__global__ void __launch_bounds__(256) lstm_step_kernel(
    const float* __restrict__ hprev, int hstride,
    const float* __restrict__ Wh,
    float* __restrict__ out, int t) {

    __shared__ float Hs[64][33];   // h_prev tile  [row n][k]
    __shared__ float Ws[32][33];   // Wh tile      [k][acol], acol = gate*8 + j
    __shared__ float At[64][32];   // a tile for gate epilogue

    int tid = threadIdx.x;
    int hb = blockIdx.x * 8;       // base h-index of this block

    int tx = tid & 15;             // column pair: cols {2tx, 2tx+1}
    int ty = tid >> 4;             // row quad:    rows {4ty..4ty+3}

    // load mappings
    int hn = tid >> 2;             // 0..63  (h row)
    int hk = (tid & 3) * 8;        // 0,8,16,24 (k offset; 2 float4 each)
    int wk = tid >> 3;             // 0..31  (k row of Wh tile)
    int wj = tid & 7;              // 0..7   (within-gate column)

    const float* hp  = hprev + (size_t)hn * hstride + hk;
    const float* wp0 = Wh + (size_t)wk * G4 + hb + wj;

    float acc[4][2];
#pragma unroll
    for (int i = 0; i < 4; i++) { acc[i][0] = 0.0f; acc[i][1] = 0.0f; }

    for (int k0 = 0; k0 < Hh; k0 += 32) {
        float4 h4a = *(const float4*)(hp + k0);
        float4 h4b = *(const float4*)(hp + k0 + 4);
        const float* wp = wp0 + (size_t)k0 * G4;
        float w0 = wp[0];
        float w1 = wp[1024];
        float w2 = wp[2048];
        float w3 = wp[3072];

        Hs[hn][hk + 0] = h4a.x; Hs[hn][hk + 1] = h4a.y;
        Hs[hn][hk + 2] = h4a.z; Hs[hn][hk + 3] = h4a.w;
        Hs[hn][hk + 4] = h4b.x; Hs[hn][hk + 5] = h4b.y;
        Hs[hn][hk + 6] = h4b.z; Hs[hn][hk + 7] = h4b.w;
        Ws[wk][wj]      = w0;
        Ws[wk][8 + wj]  = w1;
        Ws[wk][16 + wj] = w2;
        Ws[wk][24 + wj] = w3;
        __syncthreads();

#pragma unroll
        for (int kk = 0; kk < 32; kk++) {
            float h0 = Hs[ty * 4 + 0][kk];
            float h1 = Hs[ty * 4 + 1][kk];
            float h2 = Hs[ty * 4 + 2][kk];
            float h3 = Hs[ty * 4 + 3][kk];
            float wa = Ws[kk][tx * 2 + 0];
            float wb = Ws[kk][tx * 2 + 1];
            acc[0][0] += h0 * wa;  acc[0][1] += h0 * wb;
            acc[1][0] += h1 * wa;  acc[1][1] += h1 * wb;
            acc[2][0] += h2 * wa;  acc[2][1] += h2 * wb;
            acc[3][0] += h3 * wa;  acc[3][1] += h3 * wb;
        }
        __syncthreads();
    }

    // stage a-tile to smem for cross-thread gate fusion
#pragma unroll
    for (int i = 0; i < 4; i++) {
        At[ty * 4 + i][tx * 2 + 0] = acc[i][0];
        At[ty * 4 + i][tx * 2 + 1] = acc[i][1];
    }
    __syncthreads();

    // gates + state update: 512 items (n, jj), 2 per thread
#pragma unroll
    for (int itx = 0; itx < 2; itx++) {
        int item = tid + itx * 256;
        int n  = item >> 3;
        int jj = item & 7;

        const float* xwr = g_xw + ((size_t)(n * Tt + t)) * G4 + hb + jj;
        float a0 = At[n][jj]       + xwr[0];       // i
        float a1 = At[n][8 + jj]   + xwr[1024];    // f
        float a2 = At[n][16 + jj]  + xwr[2048];    // o
        float a3 = At[n][24 + jj]  + xwr[3072];    // g

        float iv = 1.0f / (1.0f + expf(-a0));
        float fv = 1.0f / (1.0f + expf(-a1));
        float ov = 1.0f / (1.0f + expf(-a2));
        float gv = tanhf(a3);

        int hcol = hb + jj;
        float cp = g_c[n * Hh + hcol];
        float cn = fv * cp + iv * gv;
        float hv = ov * tanhf(cn);

        g_c[n * Hh + hcol] = cn;
        out[((size_t)n * Tt + t) * Hh + hcol] = hv;
    }
}

// ---------------------------------------------------------------------------
// launch
// ---------------------------------------------------------------------------
extern "C" void kernel_launch(void* const* d_in, const int* in_sizes, int n_in,
                              void* d_out, int out_size) {
    const float* x  = (const float*)d_in[0];   // [N,T,D]
    const float* h0 = (const float*)d_in[1];   // [N,H]
    const float* Wx = (const float*)d_in[2];   // [D,4H]
    const float* Wh = (const float*)d_in[3];   // [H,4H]
    const float* b  = (const float*)d_in[4];   // [4H]
    float* out = (float*)d_out;                // [N,T,H]

    zero_c_kernel<<<(Nn * Hh + 255) / 256, 256>>>();

    dim3 g1(G4 / 128, (Nn * Tt) / 128);        // (32, 256)
    sgemm_xw<<<g1, 256>>>(x, Wx, b);

    for (int t = 0; t < Tt; t++) {
        const float* hprev = (t == 0) ? h0 : (const float*)(out + (size_t)(t - 1) * Hh);
        int hstride = (t == 0) ? Hh : Tt * Hh;
        lstm_step_kernel<<<128, 256>>>(hprev, hstride, Wh, out, t);
    }
}